// round 1
// baseline (speedup 1.0000x reference)
#include <cuda_runtime.h>
#include <cuda_bf16.h>
#include <math.h>
#include <stdint.h>

#define TOKENS 16384
#define DDIM   2048
#define NEXP   64
#define HDIM   1024

// Output layout (float32, tuple order flattened):
// idx [16384*2] | scores [16384*2] | probs [16384*64] | importance [64] | load [64]
#define OFF_IDX   0
#define OFF_SC    32768
#define OFF_P     65536
#define OFF_IMP   1114112
#define OFF_LOAD  1114176

// ---------------- scratch (device globals: no runtime allocation) ----------------
__device__ __nv_bfloat16 g_h[(size_t)TOKENS * DDIM];     // LN output, bf16
__device__ __nv_bfloat16 g_w1[(size_t)HDIM * DDIM];      // W1 in bf16
__device__ float g_logits[(size_t)TOKENS * NEXP];        // base logits fp32
__device__ float g_diffpre[TOKENS];                      // pre-sigmoid difficulty
__device__ int   g_loadcnt[NEXP];

// ---------------- zero scratch ----------------
__global__ void zero_kernel() {
    int i = blockIdx.x * blockDim.x + threadIdx.x;
    if (i < TOKENS) g_diffpre[i] = 0.f;
    if (i < NEXP)   g_loadcnt[i] = 0;
}

// ---------------- W1 fp32 -> bf16 ----------------
__global__ void cvt_w1_kernel(const float* __restrict__ W1) {
    int i = blockIdx.x * blockDim.x + threadIdx.x;
    g_w1[i] = __float2bfloat16(W1[i]);
}

// ---------------- LayerNorm: x -> h (bf16) ----------------
__global__ void ln_kernel(const float* __restrict__ x,
                          const float* __restrict__ gamma,
                          const float* __restrict__ beta) {
    int t = blockIdx.x;
    int tid = threadIdx.x;
    const float* xr = x + (size_t)t * DDIM;

    float4 va = *(const float4*)(xr + tid * 8);
    float4 vb = *(const float4*)(xr + tid * 8 + 4);
    float s = va.x + va.y + va.z + va.w + vb.x + vb.y + vb.z + vb.w;
    float q = va.x*va.x + va.y*va.y + va.z*va.z + va.w*va.w
            + vb.x*vb.x + vb.y*vb.y + vb.z*vb.z + vb.w*vb.w;
    #pragma unroll
    for (int off = 16; off; off >>= 1) {
        s += __shfl_xor_sync(0xffffffffu, s, off);
        q += __shfl_xor_sync(0xffffffffu, q, off);
    }
    __shared__ float ss[8], sq[8];
    int w = tid >> 5, l = tid & 31;
    if (l == 0) { ss[w] = s; sq[w] = q; }
    __syncthreads();
    if (w == 0) {
        float a = (l < 8) ? ss[l] : 0.f;
        float b = (l < 8) ? sq[l] : 0.f;
        #pragma unroll
        for (int off = 4; off; off >>= 1) {
            a += __shfl_xor_sync(0xffffffffu, a, off);
            b += __shfl_xor_sync(0xffffffffu, b, off);
        }
        if (l == 0) { ss[0] = a; sq[0] = b; }
    }
    __syncthreads();
    float mean = ss[0] * (1.f / DDIM);
    float var  = sq[0] * (1.f / DDIM) - mean * mean;
    float rstd = rsqrtf(var + 1e-5f);

    float4 ga = *(const float4*)(gamma + tid * 8);
    float4 gb = *(const float4*)(gamma + tid * 8 + 4);
    float4 ba = *(const float4*)(beta + tid * 8);
    float4 bb = *(const float4*)(beta + tid * 8 + 4);

    __align__(16) __nv_bfloat16 hb[8];
    hb[0] = __float2bfloat16((va.x - mean) * rstd * ga.x + ba.x);
    hb[1] = __float2bfloat16((va.y - mean) * rstd * ga.y + ba.y);
    hb[2] = __float2bfloat16((va.z - mean) * rstd * ga.z + ba.z);
    hb[3] = __float2bfloat16((va.w - mean) * rstd * ga.w + ba.w);
    hb[4] = __float2bfloat16((vb.x - mean) * rstd * gb.x + bb.x);
    hb[5] = __float2bfloat16((vb.y - mean) * rstd * gb.y + bb.y);
    hb[6] = __float2bfloat16((vb.z - mean) * rstd * gb.z + bb.z);
    hb[7] = __float2bfloat16((vb.w - mean) * rstd * gb.w + bb.w);
    *(uint4*)(&g_h[(size_t)t * DDIM + tid * 8]) = *(uint4*)hb;
}

// ---------------- base logits: fp32 SIMT GEMM  M=16384 N=64 K=2048 ----------------
// BM=128, BN=64(all experts), BK=32, 128 threads, TM=8, TN=8
__global__ __launch_bounds__(128)
void logits_kernel(const float* __restrict__ x, const float* __restrict__ Wg) {
    __shared__ __align__(16) float Xs[32][132];   // [kk][m], stride 132 (16B-mult)
    __shared__ __align__(16) float Ws[32][68];    // [kk][n]
    int bm = blockIdx.x;
    int tid = threadIdx.x;
    int tx = tid & 7;     // n group
    int ty = tid >> 3;    // m group (16)

    float acc[8][8];
    #pragma unroll
    for (int i = 0; i < 8; i++)
        #pragma unroll
        for (int j = 0; j < 8; j++) acc[i][j] = 0.f;

    for (int k0 = 0; k0 < DDIM; k0 += 32) {
        #pragma unroll
        for (int c = tid; c < 1024; c += 128) {
            int r = c >> 3, qq = c & 7;
            float4 v = *(const float4*)(x + (size_t)(bm * 128 + r) * DDIM + k0 + qq * 4);
            Xs[qq*4+0][r] = v.x; Xs[qq*4+1][r] = v.y;
            Xs[qq*4+2][r] = v.z; Xs[qq*4+3][r] = v.w;
        }
        #pragma unroll
        for (int c = tid; c < 512; c += 128) {
            int r = c >> 3, qq = c & 7;
            float4 v = *(const float4*)(Wg + (size_t)r * DDIM + k0 + qq * 4);
            Ws[qq*4+0][r] = v.x; Ws[qq*4+1][r] = v.y;
            Ws[qq*4+2][r] = v.z; Ws[qq*4+3][r] = v.w;
        }
        __syncthreads();
        #pragma unroll
        for (int kk = 0; kk < 32; kk++) {
            float a[8], b[8];
            *(float4*)(a)     = *(const float4*)&Xs[kk][ty * 8];
            *(float4*)(a + 4) = *(const float4*)&Xs[kk][ty * 8 + 4];
            *(float4*)(b)     = *(const float4*)&Ws[kk][tx * 8];
            *(float4*)(b + 4) = *(const float4*)&Ws[kk][tx * 8 + 4];
            #pragma unroll
            for (int i = 0; i < 8; i++)
                #pragma unroll
                for (int j = 0; j < 8; j++) acc[i][j] = fmaf(a[i], b[j], acc[i][j]);
        }
        __syncthreads();
    }
    #pragma unroll
    for (int i = 0; i < 8; i++)
        #pragma unroll
        for (int j = 0; j < 8; j++)
            g_logits[(size_t)(bm * 128 + ty * 8 + i) * NEXP + tx * 8 + j] = acc[i][j];
}

// ---------------- bf16 MMA GEMM + GELU + W2 reduce -> diff_pre ----------------
// M=16384, N=1024, K=2048. BM=128, BN=128, BK=32, 8 warps (2m x 4n), warp 64x32.
#define AST 40   // smem row stride in bf16 elems (80B, 16B-aligned, conflict-free)

__device__ __forceinline__ float gelu_exact(float v) {
    return 0.5f * v * (1.0f + erff(v * 0.70710678118654752440f));
}

__global__ __launch_bounds__(256)
void gemm1_kernel(const float* __restrict__ W2) {
    __shared__ __align__(16) __nv_bfloat16 As[128 * AST];
    __shared__ __align__(16) __nv_bfloat16 Bs[128 * AST];
    int bn = blockIdx.x, bm = blockIdx.y;
    int tid = threadIdx.x;
    int warp = tid >> 5, lane = tid & 31;
    int wm = (warp >> 2) * 64;   // 0 or 64
    int wn = (warp & 3) * 32;    // 0,32,64,96

    float acc[4][4][4];
    #pragma unroll
    for (int i = 0; i < 4; i++)
        #pragma unroll
        for (int j = 0; j < 4; j++)
            #pragma unroll
            for (int r = 0; r < 4; r++) acc[i][j][r] = 0.f;

    const __nv_bfloat16* Ag = g_h  + (size_t)(bm * 128) * DDIM;
    const __nv_bfloat16* Bg = g_w1 + (size_t)(bn * 128) * DDIM;

    for (int k0 = 0; k0 < DDIM; k0 += 32) {
        #pragma unroll
        for (int c = tid; c < 512; c += 256) {
            int r = c >> 2, c4 = c & 3;
            *(uint4*)&As[r * AST + c4 * 8] = *(const uint4*)(Ag + (size_t)r * DDIM + k0 + c4 * 8);
            *(uint4*)&Bs[r * AST + c4 * 8] = *(const uint4*)(Bg + (size_t)r * DDIM + k0 + c4 * 8);
        }
        __syncthreads();
        #pragma unroll
        for (int ks = 0; ks < 2; ks++) {
            uint32_t af[4][4], bf[4][2];
            int arow = wm + (lane >> 2);
            int colb = (lane & 3) * 2 + ks * 16;
            #pragma unroll
            for (int i = 0; i < 4; i++) {
                const __nv_bfloat16* p = &As[(arow + i * 16) * AST + colb];
                af[i][0] = *(const uint32_t*)(p);
                af[i][1] = *(const uint32_t*)(p + 8 * AST);
                af[i][2] = *(const uint32_t*)(p + 8);
                af[i][3] = *(const uint32_t*)(p + 8 * AST + 8);
            }
            int nrow = wn + (lane >> 2);
            int kb = (lane & 3) * 2 + ks * 16;
            #pragma unroll
            for (int j = 0; j < 4; j++) {
                const __nv_bfloat16* p = &Bs[(nrow + j * 8) * AST + kb];
                bf[j][0] = *(const uint32_t*)(p);
                bf[j][1] = *(const uint32_t*)(p + 8);
            }
            #pragma unroll
            for (int i = 0; i < 4; i++)
                #pragma unroll
                for (int j = 0; j < 4; j++) {
                    asm volatile(
                        "mma.sync.aligned.m16n8k16.row.col.f32.bf16.bf16.f32 "
                        "{%0,%1,%2,%3}, {%4,%5,%6,%7}, {%8,%9}, {%0,%1,%2,%3};\n"
                        : "+f"(acc[i][j][0]), "+f"(acc[i][j][1]),
                          "+f"(acc[i][j][2]), "+f"(acc[i][j][3])
                        : "r"(af[i][0]), "r"(af[i][1]), "r"(af[i][2]), "r"(af[i][3]),
                          "r"(bf[j][0]), "r"(bf[j][1]));
                }
        }
        __syncthreads();
    }

    // epilogue: gelu(h1) * W2[n], reduce over this block's n-slice, atomic into diff_pre
    float part0[4] = {0.f, 0.f, 0.f, 0.f};
    float part1[4] = {0.f, 0.f, 0.f, 0.f};
    #pragma unroll
    for (int j = 0; j < 4; j++) {
        int n = bn * 128 + wn + j * 8 + (lane & 3) * 2;
        float w20 = W2[n], w21 = W2[n + 1];
        #pragma unroll
        for (int i = 0; i < 4; i++) {
            part0[i] += gelu_exact(acc[i][j][0]) * w20 + gelu_exact(acc[i][j][1]) * w21;
            part1[i] += gelu_exact(acc[i][j][2]) * w20 + gelu_exact(acc[i][j][3]) * w21;
        }
    }
    // reduce across the 4 lanes sharing the same row (lane^1, lane^2 keep lane>>2)
    #pragma unroll
    for (int i = 0; i < 4; i++) {
        part0[i] += __shfl_xor_sync(0xffffffffu, part0[i], 1);
        part0[i] += __shfl_xor_sync(0xffffffffu, part0[i], 2);
        part1[i] += __shfl_xor_sync(0xffffffffu, part1[i], 1);
        part1[i] += __shfl_xor_sync(0xffffffffu, part1[i], 2);
    }
    if ((lane & 3) == 0) {
        int mbase = bm * 128 + wm + (lane >> 2);
        #pragma unroll
        for (int i = 0; i < 4; i++) {
            atomicAdd(&g_diffpre[mbase + i * 16], part0[i]);
            atomicAdd(&g_diffpre[mbase + i * 16 + 8], part1[i]);
        }
    }
}

// ---------------- finalize: sigmoid, modulate, softmax, top-2, outputs ----------------
__global__ void finalize_kernel(float* __restrict__ out) {
    int t = blockIdx.x * 8 + (threadIdx.x >> 5);
    int lane = threadIdx.x & 31;

    float2 lg = *(const float2*)&g_logits[(size_t)t * NEXP + lane * 2];
    float dp = g_diffpre[t];
    float diff = 1.f / (1.f + expf(-dp));
    float denom = 1.f + diff;          // TEMP = 1
    float l0 = lg.x / denom;
    float l1 = lg.y / denom;

    // softmax
    float m = fmaxf(l0, l1);
    #pragma unroll
    for (int off = 16; off; off >>= 1) m = fmaxf(m, __shfl_xor_sync(0xffffffffu, m, off));
    float e0 = expf(l0 - m), e1 = expf(l1 - m);
    float s = e0 + e1;
    #pragma unroll
    for (int off = 16; off; off >>= 1) s += __shfl_xor_sync(0xffffffffu, s, off);
    float p0 = e0 / s, p1 = e1 / s;
    *(float2*)&out[OFF_P + (size_t)t * NEXP + lane * 2] = make_float2(p0, p1);

    // top-1 (max value, lowest index on tie — matches lax.top_k)
    float bv; int bi;
    if (l1 > l0) { bv = l1; bi = lane * 2 + 1; } else { bv = l0; bi = lane * 2; }
    #pragma unroll
    for (int off = 16; off; off >>= 1) {
        float ov = __shfl_xor_sync(0xffffffffu, bv, off);
        int   oi = __shfl_xor_sync(0xffffffffu, bi, off);
        if (ov > bv || (ov == bv && oi < bi)) { bv = ov; bi = oi; }
    }
    int top1 = bi;
    // top-2: exclude top1
    float c0 = (lane * 2     == top1) ? -INFINITY : l0;
    float c1 = (lane * 2 + 1 == top1) ? -INFINITY : l1;
    float bv2; int bi2;
    if (c1 > c0) { bv2 = c1; bi2 = lane * 2 + 1; } else { bv2 = c0; bi2 = lane * 2; }
    #pragma unroll
    for (int off = 16; off; off >>= 1) {
        float ov = __shfl_xor_sync(0xffffffffu, bv2, off);
        int   oi = __shfl_xor_sync(0xffffffffu, bi2, off);
        if (ov > bv2 || (ov == bv2 && oi < bi2)) { bv2 = ov; bi2 = oi; }
    }
    int top2 = bi2;

    // gather probs at top1/top2 via shfl
    float sel1 = (top1 & 1) ? p1 : p0;
    float pt1 = __shfl_sync(0xffffffffu, sel1, top1 >> 1);
    float sel2 = (top2 & 1) ? p1 : p0;
    float pt2 = __shfl_sync(0xffffffffu, sel2, top2 >> 1);

    // straight-through: (hard - p) + p, faithful to reference fp math
    float s1 = (1.0f - pt1) + pt1;
    float s2 = (1.0f - pt2) + pt2;
    float dsum = fmaxf(s1 + s2, 1e-9f);

    if (lane == 0) {
        out[OFF_IDX + t * 2]     = (float)top1;
        out[OFF_IDX + t * 2 + 1] = (float)top2;
        out[OFF_SC + t * 2]      = s1 / dsum;
        out[OFF_SC + t * 2 + 1]  = s2 / dsum;
        atomicAdd(&g_loadcnt[top1], 1);
        atomicAdd(&g_loadcnt[top2], 1);
    }
}

// ---------------- importance / load ----------------
__global__ void stats_kernel(float* __restrict__ out) {
    int e = blockIdx.x;
    int tid = threadIdx.x;
    float s = 0.f;
    for (int t = tid; t < TOKENS; t += 256)
        s += out[OFF_P + (size_t)t * NEXP + e];
    #pragma unroll
    for (int off = 16; off; off >>= 1) s += __shfl_xor_sync(0xffffffffu, s, off);
    __shared__ float red[8];
    int w = tid >> 5, l = tid & 31;
    if (l == 0) red[w] = s;
    __syncthreads();
    if (tid == 0) {
        float tot = 0.f;
        #pragma unroll
        for (int i = 0; i < 8; i++) tot += red[i];
        out[OFF_IMP + e]  = tot * (1.f / TOKENS);
        out[OFF_LOAD + e] = (float)g_loadcnt[e] * (1.f / TOKENS);
    }
}

// ---------------- launch ----------------
extern "C" void kernel_launch(void* const* d_in, const int* in_sizes, int n_in,
                              void* d_out, int out_size) {
    const float* x     = (const float*)d_in[0];
    const float* Wg    = (const float*)d_in[1];
    const float* gamma = (const float*)d_in[2];
    const float* beta  = (const float*)d_in[3];
    const float* W1    = (const float*)d_in[4];
    const float* W2    = (const float*)d_in[5];
    float* out = (float*)d_out;

    zero_kernel<<<64, 256>>>();
    cvt_w1_kernel<<<(HDIM * DDIM) / 256, 256>>>(W1);
    ln_kernel<<<TOKENS, 256>>>(x, gamma, beta);
    logits_kernel<<<TOKENS / 128, 128>>>(x, Wg);
    dim3 g3(HDIM / 128, TOKENS / 128);
    gemm1_kernel<<<g3, 256>>>(W2);
    finalize_kernel<<<TOKENS / 8, 256>>>(out);
    stats_kernel<<<NEXP, 256>>>(out);
}

// round 2
// speedup vs baseline: 1.5186x; 1.5186x over previous
#include <cuda_runtime.h>
#include <cuda_bf16.h>
#include <math.h>
#include <stdint.h>

#define TOKENS 16384
#define DDIM   2048
#define NEXP   64
#define HDIM   1024

// Output layout (float32): idx [16384*2] | scores [16384*2] | probs [16384*64] | imp [64] | load [64]
#define OFF_IDX   0
#define OFF_SC    32768
#define OFF_P     65536
#define OFF_IMP   1114112
#define OFF_LOAD  1114176

// ---------------- scratch ----------------
__device__ __nv_bfloat16 g_h[(size_t)TOKENS * DDIM];
__device__ __nv_bfloat16 g_w1[(size_t)HDIM * DDIM];
__device__ __nv_bfloat16 g_wg_hi[(size_t)NEXP * DDIM];
__device__ __nv_bfloat16 g_wg_lo[(size_t)NEXP * DDIM];
__device__ float g_logits[(size_t)TOKENS * NEXP];
__device__ float g_diffpre[TOKENS];
__device__ int   g_loadcnt[NEXP];

__global__ void zero_kernel() {
    int i = blockIdx.x * blockDim.x + threadIdx.x;
    if (i < TOKENS) g_diffpre[i] = 0.f;
    if (i < NEXP)   g_loadcnt[i] = 0;
}

__global__ void cvt_w1_kernel(const float* __restrict__ W1) {
    int i = blockIdx.x * blockDim.x + threadIdx.x;
    g_w1[i] = __float2bfloat16(W1[i]);
}

__global__ void cvt_wg_kernel(const float* __restrict__ Wg) {
    int i = blockIdx.x * blockDim.x + threadIdx.x;
    float v = Wg[i];
    __nv_bfloat16 hi = __float2bfloat16(v);
    g_wg_hi[i] = hi;
    g_wg_lo[i] = __float2bfloat16(v - __bfloat162float(hi));
}

// =========================================================================
// Fused LayerNorm + base-logits GEMM (bf16x3 split, exact-ish fp32)
// One CTA = 128 tokens. 256 threads (8 warps). K chunks of 32.
// =========================================================================
#define AST 40

__global__ __launch_bounds__(256)
void fused_ln_logits(const float* __restrict__ x,
                     const float* __restrict__ gamma,
                     const float* __restrict__ beta) {
    __shared__ __align__(16) __nv_bfloat16 Ah[128 * AST];
    __shared__ __align__(16) __nv_bfloat16 Al[128 * AST];
    __shared__ __align__(16) __nv_bfloat16 Wh[64 * AST];
    __shared__ __align__(16) __nv_bfloat16 Wl[64 * AST];
    __shared__ float sS[128 * 8], sQ[128 * 8];
    __shared__ float smean[128], srstd[128];

    int tile = blockIdx.x;
    int tid = threadIdx.x;
    int warp = tid >> 5, lane = tid & 31;
    const float* xb = x + (size_t)tile * 128 * DDIM;

    int lr = tid >> 3;          // 0..31, row base
    int lc = (tid & 7) * 4;     // col (0..28)
    int wr = tid >> 2;          // 0..63
    int wc = (tid & 3) * 8;     // 0,8,16,24

    float s[4] = {0.f, 0.f, 0.f, 0.f}, q[4] = {0.f, 0.f, 0.f, 0.f};
    float acc[8][4];
    #pragma unroll
    for (int j = 0; j < 8; j++)
        #pragma unroll
        for (int r = 0; r < 4; r++) acc[j][r] = 0.f;

    // prefetch chunk 0 into registers
    float4 v[4];
    #pragma unroll
    for (int i = 0; i < 4; i++)
        v[i] = *(const float4*)&xb[(size_t)(lr + i * 32) * DDIM + lc];
    uint4 wh = *(const uint4*)&g_wg_hi[(size_t)wr * DDIM + wc];
    uint4 wl = *(const uint4*)&g_wg_lo[(size_t)wr * DDIM + wc];

    for (int kc = 0; kc < 64; kc++) {
        // stage registers -> smem
        *(uint4*)&Wh[wr * AST + wc] = wh;
        *(uint4*)&Wl[wr * AST + wc] = wl;
        #pragma unroll
        for (int i = 0; i < 4; i++) {
            float4 t4 = v[i];
            s[i] += t4.x + t4.y + t4.z + t4.w;
            q[i] += t4.x * t4.x + t4.y * t4.y + t4.z * t4.z + t4.w * t4.w;
            __nv_bfloat16 b0 = __float2bfloat16(t4.x);
            __nv_bfloat16 b1 = __float2bfloat16(t4.y);
            __nv_bfloat16 b2 = __float2bfloat16(t4.z);
            __nv_bfloat16 b3 = __float2bfloat16(t4.w);
            float r0 = t4.x - __bfloat162float(b0);
            float r1 = t4.y - __bfloat162float(b1);
            float r2 = t4.z - __bfloat162float(b2);
            float r3 = t4.w - __bfloat162float(b3);
            __nv_bfloat162 ph0; ph0.x = b0; ph0.y = b1;
            __nv_bfloat162 ph1; ph1.x = b2; ph1.y = b3;
            __nv_bfloat162 pl0 = __floats2bfloat162_rn(r0, r1);
            __nv_bfloat162 pl1 = __floats2bfloat162_rn(r2, r3);
            uint2 uh; uh.x = *(uint32_t*)&ph0; uh.y = *(uint32_t*)&ph1;
            uint2 ul; ul.x = *(uint32_t*)&pl0; ul.y = *(uint32_t*)&pl1;
            int rr = lr + i * 32;
            *(uint2*)&Ah[rr * AST + lc] = uh;
            *(uint2*)&Al[rr * AST + lc] = ul;
        }
        __syncthreads();

        // prefetch next chunk (latency hidden behind MMA)
        if (kc < 63) {
            int k0n = (kc + 1) * 32;
            #pragma unroll
            for (int i = 0; i < 4; i++)
                v[i] = *(const float4*)&xb[(size_t)(lr + i * 32) * DDIM + k0n + lc];
            wh = *(const uint4*)&g_wg_hi[(size_t)wr * DDIM + k0n + wc];
            wl = *(const uint4*)&g_wg_lo[(size_t)wr * DDIM + k0n + wc];
        }

        // MMA: warp owns rows [warp*16, warp*16+16), all 64 experts
        #pragma unroll
        for (int ks = 0; ks < 2; ks++) {
            int arow = warp * 16 + (lane >> 2);
            int colb = (lane & 3) * 2 + ks * 16;
            const __nv_bfloat16* pa = &Ah[arow * AST + colb];
            const __nv_bfloat16* pal = &Al[arow * AST + colb];
            uint32_t ah[4], al[4];
            ah[0] = *(const uint32_t*)(pa);
            ah[1] = *(const uint32_t*)(pa + 8 * AST);
            ah[2] = *(const uint32_t*)(pa + 8);
            ah[3] = *(const uint32_t*)(pa + 8 * AST + 8);
            al[0] = *(const uint32_t*)(pal);
            al[1] = *(const uint32_t*)(pal + 8 * AST);
            al[2] = *(const uint32_t*)(pal + 8);
            al[3] = *(const uint32_t*)(pal + 8 * AST + 8);
            #pragma unroll
            for (int j = 0; j < 8; j++) {
                int brow = j * 8 + (lane >> 2);
                const __nv_bfloat16* pb = &Wh[brow * AST + colb];
                const __nv_bfloat16* pbl = &Wl[brow * AST + colb];
                uint32_t bh0 = *(const uint32_t*)(pb);
                uint32_t bh1 = *(const uint32_t*)(pb + 8);
                uint32_t bl0 = *(const uint32_t*)(pbl);
                uint32_t bl1 = *(const uint32_t*)(pbl + 8);
                asm volatile(
                    "mma.sync.aligned.m16n8k16.row.col.f32.bf16.bf16.f32 "
                    "{%0,%1,%2,%3}, {%4,%5,%6,%7}, {%8,%9}, {%0,%1,%2,%3};\n"
                    : "+f"(acc[j][0]), "+f"(acc[j][1]), "+f"(acc[j][2]), "+f"(acc[j][3])
                    : "r"(ah[0]), "r"(ah[1]), "r"(ah[2]), "r"(ah[3]), "r"(bh0), "r"(bh1));
                asm volatile(
                    "mma.sync.aligned.m16n8k16.row.col.f32.bf16.bf16.f32 "
                    "{%0,%1,%2,%3}, {%4,%5,%6,%7}, {%8,%9}, {%0,%1,%2,%3};\n"
                    : "+f"(acc[j][0]), "+f"(acc[j][1]), "+f"(acc[j][2]), "+f"(acc[j][3])
                    : "r"(ah[0]), "r"(ah[1]), "r"(ah[2]), "r"(ah[3]), "r"(bl0), "r"(bl1));
                asm volatile(
                    "mma.sync.aligned.m16n8k16.row.col.f32.bf16.bf16.f32 "
                    "{%0,%1,%2,%3}, {%4,%5,%6,%7}, {%8,%9}, {%0,%1,%2,%3};\n"
                    : "+f"(acc[j][0]), "+f"(acc[j][1]), "+f"(acc[j][2]), "+f"(acc[j][3])
                    : "r"(al[0]), "r"(al[1]), "r"(al[2]), "r"(al[3]), "r"(bh0), "r"(bh1));
            }
        }
        __syncthreads();
    }

    // LN stats reduction
    #pragma unroll
    for (int i = 0; i < 4; i++) {
        sS[(lr + i * 32) * 8 + (tid & 7)] = s[i];
        sQ[(lr + i * 32) * 8 + (tid & 7)] = q[i];
    }
    __syncthreads();
    if (tid < 128) {
        float ts = 0.f, tq = 0.f;
        #pragma unroll
        for (int j = 0; j < 8; j++) { ts += sS[tid * 8 + j]; tq += sQ[tid * 8 + j]; }
        float mean = ts * (1.f / DDIM);
        float var  = tq * (1.f / DDIM) - mean * mean;
        smean[tid] = mean;
        srstd[tid] = rsqrtf(var + 1e-5f);
    }
    __syncthreads();

    // pass 2: apply LN, write h (x re-read is L2-hot)
    for (int kc = 0; kc < 64; kc++) {
        int k0 = kc * 32;
        float4 g4 = *(const float4*)&gamma[k0 + lc];
        float4 b4 = *(const float4*)&beta[k0 + lc];
        #pragma unroll
        for (int i = 0; i < 4; i++) {
            int rr = lr + i * 32;
            float4 t4 = *(const float4*)&xb[(size_t)rr * DDIM + k0 + lc];
            float mean = smean[rr], rstd = srstd[rr];
            __nv_bfloat162 p0 = __floats2bfloat162_rn(
                (t4.x - mean) * rstd * g4.x + b4.x, (t4.y - mean) * rstd * g4.y + b4.y);
            __nv_bfloat162 p1 = __floats2bfloat162_rn(
                (t4.z - mean) * rstd * g4.z + b4.z, (t4.w - mean) * rstd * g4.w + b4.w);
            uint2 u; u.x = *(uint32_t*)&p0; u.y = *(uint32_t*)&p1;
            *(uint2*)&g_h[(size_t)(tile * 128 + rr) * DDIM + k0 + lc] = u;
        }
    }

    // write logits
    #pragma unroll
    for (int j = 0; j < 8; j++) {
        int row = tile * 128 + warp * 16 + (lane >> 2);
        int col = j * 8 + (lane & 3) * 2;
        float2 c01; c01.x = acc[j][0]; c01.y = acc[j][1];
        float2 c23; c23.x = acc[j][2]; c23.y = acc[j][3];
        *(float2*)&g_logits[(size_t)row * NEXP + col] = c01;
        *(float2*)&g_logits[(size_t)(row + 8) * NEXP + col] = c23;
    }
}

// =========================================================================
// bf16 MMA GEMM + GELU + W2 reduce -> diff_pre  (cp.async double-buffered)
// =========================================================================
__device__ __forceinline__ float gelu_exact(float v) {
    return 0.5f * v * (1.0f + erff(v * 0.70710678118654752440f));
}

__global__ __launch_bounds__(256)
void gemm1_kernel(const float* __restrict__ W2) {
    __shared__ __align__(16) __nv_bfloat16 As[2][128 * AST];
    __shared__ __align__(16) __nv_bfloat16 Bs[2][128 * AST];
    int bn = blockIdx.x, bm = blockIdx.y;
    int tid = threadIdx.x;
    int warp = tid >> 5, lane = tid & 31;
    int wm = (warp >> 2) * 64;
    int wn = (warp & 3) * 32;

    float acc[4][4][4];
    #pragma unroll
    for (int i = 0; i < 4; i++)
        #pragma unroll
        for (int j = 0; j < 4; j++)
            #pragma unroll
            for (int r = 0; r < 4; r++) acc[i][j][r] = 0.f;

    const __nv_bfloat16* Ag = g_h  + (size_t)(bm * 128) * DDIM;
    const __nv_bfloat16* Bg = g_w1 + (size_t)(bn * 128) * DDIM;

    auto stage_load = [&](int k0, int st) {
        #pragma unroll
        for (int c = tid; c < 512; c += 256) {
            int r = c >> 2, c4 = c & 3;
            uint32_t da = (uint32_t)__cvta_generic_to_shared(&As[st][r * AST + c4 * 8]);
            asm volatile("cp.async.cg.shared.global [%0], [%1], 16;\n"
                         :: "r"(da), "l"(Ag + (size_t)r * DDIM + k0 + c4 * 8));
            uint32_t db = (uint32_t)__cvta_generic_to_shared(&Bs[st][r * AST + c4 * 8]);
            asm volatile("cp.async.cg.shared.global [%0], [%1], 16;\n"
                         :: "r"(db), "l"(Bg + (size_t)r * DDIM + k0 + c4 * 8));
        }
        asm volatile("cp.async.commit_group;\n");
    };

    stage_load(0, 0);
    int st = 0;
    for (int k0 = 0; k0 < DDIM; k0 += 32) {
        if (k0 + 32 < DDIM) {
            stage_load(k0 + 32, st ^ 1);
            asm volatile("cp.async.wait_group 1;\n");
        } else {
            asm volatile("cp.async.wait_group 0;\n");
        }
        __syncthreads();
        #pragma unroll
        for (int ks = 0; ks < 2; ks++) {
            uint32_t af[4][4], bf[4][2];
            int arow = wm + (lane >> 2);
            int colb = (lane & 3) * 2 + ks * 16;
            #pragma unroll
            for (int i = 0; i < 4; i++) {
                const __nv_bfloat16* p = &As[st][(arow + i * 16) * AST + colb];
                af[i][0] = *(const uint32_t*)(p);
                af[i][1] = *(const uint32_t*)(p + 8 * AST);
                af[i][2] = *(const uint32_t*)(p + 8);
                af[i][3] = *(const uint32_t*)(p + 8 * AST + 8);
            }
            int nrow = wn + (lane >> 2);
            #pragma unroll
            for (int j = 0; j < 4; j++) {
                const __nv_bfloat16* p = &Bs[st][(nrow + j * 8) * AST + colb];
                bf[j][0] = *(const uint32_t*)(p);
                bf[j][1] = *(const uint32_t*)(p + 8);
            }
            #pragma unroll
            for (int i = 0; i < 4; i++)
                #pragma unroll
                for (int j = 0; j < 4; j++) {
                    asm volatile(
                        "mma.sync.aligned.m16n8k16.row.col.f32.bf16.bf16.f32 "
                        "{%0,%1,%2,%3}, {%4,%5,%6,%7}, {%8,%9}, {%0,%1,%2,%3};\n"
                        : "+f"(acc[i][j][0]), "+f"(acc[i][j][1]),
                          "+f"(acc[i][j][2]), "+f"(acc[i][j][3])
                        : "r"(af[i][0]), "r"(af[i][1]), "r"(af[i][2]), "r"(af[i][3]),
                          "r"(bf[j][0]), "r"(bf[j][1]));
                }
        }
        __syncthreads();
        st ^= 1;
    }

    float part0[4] = {0.f, 0.f, 0.f, 0.f};
    float part1[4] = {0.f, 0.f, 0.f, 0.f};
    #pragma unroll
    for (int j = 0; j < 4; j++) {
        int n = bn * 128 + wn + j * 8 + (lane & 3) * 2;
        float w20 = W2[n], w21 = W2[n + 1];
        #pragma unroll
        for (int i = 0; i < 4; i++) {
            part0[i] += gelu_exact(acc[i][j][0]) * w20 + gelu_exact(acc[i][j][1]) * w21;
            part1[i] += gelu_exact(acc[i][j][2]) * w20 + gelu_exact(acc[i][j][3]) * w21;
        }
    }
    #pragma unroll
    for (int i = 0; i < 4; i++) {
        part0[i] += __shfl_xor_sync(0xffffffffu, part0[i], 1);
        part0[i] += __shfl_xor_sync(0xffffffffu, part0[i], 2);
        part1[i] += __shfl_xor_sync(0xffffffffu, part1[i], 1);
        part1[i] += __shfl_xor_sync(0xffffffffu, part1[i], 2);
    }
    if ((lane & 3) == 0) {
        int mbase = bm * 128 + wm + (lane >> 2);
        #pragma unroll
        for (int i = 0; i < 4; i++) {
            atomicAdd(&g_diffpre[mbase + i * 16], part0[i]);
            atomicAdd(&g_diffpre[mbase + i * 16 + 8], part1[i]);
        }
    }
}

// ---------------- finalize ----------------
__global__ void finalize_kernel(float* __restrict__ out) {
    int t = blockIdx.x * 8 + (threadIdx.x >> 5);
    int lane = threadIdx.x & 31;

    float2 lg = *(const float2*)&g_logits[(size_t)t * NEXP + lane * 2];
    float dp = g_diffpre[t];
    float diff = 1.f / (1.f + expf(-dp));
    float denom = 1.f + diff;
    float l0 = lg.x / denom;
    float l1 = lg.y / denom;

    float m = fmaxf(l0, l1);
    #pragma unroll
    for (int off = 16; off; off >>= 1) m = fmaxf(m, __shfl_xor_sync(0xffffffffu, m, off));
    float e0 = expf(l0 - m), e1 = expf(l1 - m);
    float sum = e0 + e1;
    #pragma unroll
    for (int off = 16; off; off >>= 1) sum += __shfl_xor_sync(0xffffffffu, sum, off);
    float p0 = e0 / sum, p1 = e1 / sum;
    *(float2*)&out[OFF_P + (size_t)t * NEXP + lane * 2] = make_float2(p0, p1);

    float bv; int bi;
    if (l1 > l0) { bv = l1; bi = lane * 2 + 1; } else { bv = l0; bi = lane * 2; }
    #pragma unroll
    for (int off = 16; off; off >>= 1) {
        float ov = __shfl_xor_sync(0xffffffffu, bv, off);
        int   oi = __shfl_xor_sync(0xffffffffu, bi, off);
        if (ov > bv || (ov == bv && oi < bi)) { bv = ov; bi = oi; }
    }
    int top1 = bi;
    float c0 = (lane * 2     == top1) ? -INFINITY : l0;
    float c1 = (lane * 2 + 1 == top1) ? -INFINITY : l1;
    float bv2; int bi2;
    if (c1 > c0) { bv2 = c1; bi2 = lane * 2 + 1; } else { bv2 = c0; bi2 = lane * 2; }
    #pragma unroll
    for (int off = 16; off; off >>= 1) {
        float ov = __shfl_xor_sync(0xffffffffu, bv2, off);
        int   oi = __shfl_xor_sync(0xffffffffu, bi2, off);
        if (ov > bv2 || (ov == bv2 && oi < bi2)) { bv2 = ov; bi2 = oi; }
    }
    int top2 = bi2;

    float sel1 = (top1 & 1) ? p1 : p0;
    float pt1 = __shfl_sync(0xffffffffu, sel1, top1 >> 1);
    float sel2 = (top2 & 1) ? p1 : p0;
    float pt2 = __shfl_sync(0xffffffffu, sel2, top2 >> 1);

    float s1 = (1.0f - pt1) + pt1;
    float s2 = (1.0f - pt2) + pt2;
    float dsum = fmaxf(s1 + s2, 1e-9f);

    if (lane == 0) {
        out[OFF_IDX + t * 2]     = (float)top1;
        out[OFF_IDX + t * 2 + 1] = (float)top2;
        out[OFF_SC + t * 2]      = s1 / dsum;
        out[OFF_SC + t * 2 + 1]  = s2 / dsum;
        atomicAdd(&g_loadcnt[top1], 1);
        atomicAdd(&g_loadcnt[top2], 1);
    }
}

// ---------------- importance / load ----------------
__global__ void stats_kernel(float* __restrict__ out) {
    int e = blockIdx.x;
    int tid = threadIdx.x;
    float s = 0.f;
    for (int t = tid; t < TOKENS; t += 256)
        s += out[OFF_P + (size_t)t * NEXP + e];
    #pragma unroll
    for (int off = 16; off; off >>= 1) s += __shfl_xor_sync(0xffffffffu, s, off);
    __shared__ float red[8];
    int w = tid >> 5, l = tid & 31;
    if (l == 0) red[w] = s;
    __syncthreads();
    if (tid == 0) {
        float tot = 0.f;
        #pragma unroll
        for (int i = 0; i < 8; i++) tot += red[i];
        out[OFF_IMP + e]  = tot * (1.f / TOKENS);
        out[OFF_LOAD + e] = (float)g_loadcnt[e] * (1.f / TOKENS);
    }
}

// ---------------- launch ----------------
extern "C" void kernel_launch(void* const* d_in, const int* in_sizes, int n_in,
                              void* d_out, int out_size) {
    const float* x     = (const float*)d_in[0];
    const float* Wg    = (const float*)d_in[1];
    const float* gamma = (const float*)d_in[2];
    const float* beta  = (const float*)d_in[3];
    const float* W1    = (const float*)d_in[4];
    const float* W2    = (const float*)d_in[5];
    float* out = (float*)d_out;

    zero_kernel<<<64, 256>>>();
    cvt_w1_kernel<<<(HDIM * DDIM) / 256, 256>>>(W1);
    cvt_wg_kernel<<<(NEXP * DDIM) / 256, 256>>>(Wg);
    fused_ln_logits<<<TOKENS / 128, 256>>>(x, gamma, beta);
    dim3 g3(HDIM / 128, TOKENS / 128);
    gemm1_kernel<<<g3, 256>>>(W2);
    finalize_kernel<<<TOKENS / 8, 256>>>(out);
    stats_kernel<<<NEXP, 256>>>(out);
}